// round 8
// baseline (speedup 1.0000x reference)
#include <cuda_runtime.h>

// Problem constants
#define BB   4096
#define TT   50
#define OBS  64
#define ACTD 16
#define DIN  80      // OBS + ACT
#define HH   256
#define G4   1024    // 4*H
#define NL   5
#define OUTD 64

// Kernel config
#define RPB  32            // batch rows per CTA
#define NCTA (BB / RPB)    // 128
#define NTH  512
#define SAS  36            // sA row stride in floats
#define KTOT 336

// Shared memory (floats): double-buffered A + bias cache
#define SZ_BUF (KTOT * SAS)        // 12096
#define OFF_A0 0
#define OFF_A1 (SZ_BUF)
#define OFF_SB (2 * SZ_BUF)
#define SMEM_FLOATS (OFF_SB + G4)  // 25216 floats = 100864 B

typedef unsigned long long ull;

__device__ __forceinline__ float sigf(float x) {
    return __fdividef(1.0f, 1.0f + __expf(-x));
}

// packed f32x2 (sm_103a FFMA2 — PTX-only path)
__device__ __forceinline__ void ffma2(ull &d, ull a, ull b) {
    asm("fma.rn.f32x2 %0, %1, %2, %0;" : "+l"(d) : "l"(a), "l"(b));
}
__device__ __forceinline__ ull pk2(float lo, float hi) {
    ull r; asm("mov.b64 %0, {%1, %2};" : "=l"(r) : "f"(lo), "f"(hi)); return r;
}
__device__ __forceinline__ void upk2(ull v, float &lo, float &hi) {
    asm("mov.b64 {%0, %1}, %2;" : "=f"(lo), "=f"(hi) : "l"(v));
}

__device__ __forceinline__ float gatef(float zi, float zf, float zg, float zo,
                                       float &c)
{
    const float ig = sigf(zi);
    const float fg = sigf(zf);
    const float gg = zg * sigf(zg);       // silu
    const float og = sigf(zo);
    const float cn = fg * c + ig * gg;
    c = cn;
    return og * cn * sigf(cn);            // o * silu(c_new)
}

__global__ void __launch_bounds__(NTH, 1)
lstm_fwd_kernel(const float* __restrict__ traj, const float* __restrict__ act,
                const float* __restrict__ Wi,   const float* __restrict__ Wh,
                const float* __restrict__ bh,   const float* __restrict__ mlpW,
                const float* __restrict__ mlpB, const float* __restrict__ Wout,
                const float* __restrict__ bout, float* __restrict__ out)
{
    extern __shared__ float sm[];
    float* sB = sm + OFF_SB;

    const int tid  = threadIdx.x;
    const int row0 = blockIdx.x * RPB;
    const int rgrp = tid & 7;        // 8 row groups x 4 rows
    const int cgrp = tid >> 3;       // 0..63, each owns 4 hk cols (all 256 covered)
    const int r0   = rgrp << 2;
    const int hk0  = cgrp << 2;

    float* cA = sm + OFF_A0;         // current A buffer [336][36]
    float* nA = sm + OFF_A1;         // next A buffer

    // cell state: creg[c*4 + r], c = col within thread tile (4), r = row (4)
    float creg[16];
    #pragma unroll
    for (int i = 0; i < 16; ++i) creg[i] = 0.0f;

    // init: zero h region of buf0, cache bh, load x(0)
    for (int i = tid; i < HH * SAS; i += NTH) cA[DIN * SAS + i] = 0.0f;
    for (int i = tid; i < G4; i += NTH) sB[i] = bh[i];
    for (int i = tid; i < DIN * RPB; i += NTH) {
        const int r = i & 31, k = i >> 5;
        const int row = row0 + r;
        float v;
        if (k < OBS) v = traj[((size_t)row * TT) * OBS + k];
        else         v = act [((size_t)row * TT) * ACTD + (k - OBS)];
        cA[k * SAS + r] = v;
    }
    __syncthreads();

    const float* wI = Wi + hk0;      // + k*1024 + g*256
    const float* wH = Wh + hk0;

    // ============================ LSTM over time ============================
    for (int t = 0; t < TT; ++t) {
        // acc[g*8 + cp*4 + r]: gate g, col-pair cp (cols 2cp,2cp+1), row r
        // initialized with per-gate biases (broadcast over rows)
        ull acc[32];
        #pragma unroll
        for (int g = 0; g < 4; ++g) {
            const ull b0 = pk2(sB[(g << 8) + hk0],     sB[(g << 8) + hk0 + 1]);
            const ull b1 = pk2(sB[(g << 8) + hk0 + 2], sB[(g << 8) + hk0 + 3]);
            #pragma unroll
            for (int r = 0; r < 4; ++r) {
                acc[g * 8 + 0 + r] = b0;
                acc[g * 8 + 4 + r] = b1;
            }
        }

        // x part: k = 0..79
        #pragma unroll 2
        for (int k = 0; k < DIN; ++k) {
            const float4 a = *(const float4*)(cA + k * SAS + r0);
            const ull a0 = pk2(a.x, a.x), a1 = pk2(a.y, a.y);
            const ull a2 = pk2(a.z, a.z), a3 = pk2(a.w, a.w);
            const float* wr = wI + (size_t)k * G4;
            #pragma unroll
            for (int g = 0; g < 4; ++g) {
                const ulonglong2 w = *(const ulonglong2*)(wr + (g << 8));
                ffma2(acc[g * 8 + 0], w.x, a0);
                ffma2(acc[g * 8 + 1], w.x, a1);
                ffma2(acc[g * 8 + 2], w.x, a2);
                ffma2(acc[g * 8 + 3], w.x, a3);
                ffma2(acc[g * 8 + 4], w.y, a0);
                ffma2(acc[g * 8 + 5], w.y, a1);
                ffma2(acc[g * 8 + 6], w.y, a2);
                ffma2(acc[g * 8 + 7], w.y, a3);
            }
        }
        // h part: k = 0..255 (rows DIN..335 of cA)
        #pragma unroll 2
        for (int k = 0; k < HH; ++k) {
            const float4 a = *(const float4*)(cA + (DIN + k) * SAS + r0);
            const ull a0 = pk2(a.x, a.x), a1 = pk2(a.y, a.y);
            const ull a2 = pk2(a.z, a.z), a3 = pk2(a.w, a.w);
            const float* wr = wH + (size_t)k * G4;
            #pragma unroll
            for (int g = 0; g < 4; ++g) {
                const ulonglong2 w = *(const ulonglong2*)(wr + (g << 8));
                ffma2(acc[g * 8 + 0], w.x, a0);
                ffma2(acc[g * 8 + 1], w.x, a1);
                ffma2(acc[g * 8 + 2], w.x, a2);
                ffma2(acc[g * 8 + 3], w.x, a3);
                ffma2(acc[g * 8 + 4], w.y, a0);
                ffma2(acc[g * 8 + 5], w.y, a1);
                ffma2(acc[g * 8 + 6], w.y, a2);
                ffma2(acc[g * 8 + 7], w.y, a3);
            }
        }

        // gate epilogue -> h_new straight into NEXT buffer
        #pragma unroll
        for (int cp = 0; cp < 2; ++cp) {
            #pragma unroll
            for (int r = 0; r < 4; ++r) {
                float zi0, zi1, zf0, zf1, zg0, zg1, zo0, zo1;
                upk2(acc[0 * 8 + cp * 4 + r], zi0, zi1);
                upk2(acc[1 * 8 + cp * 4 + r], zf0, zf1);
                upk2(acc[2 * 8 + cp * 4 + r], zg0, zg1);
                upk2(acc[3 * 8 + cp * 4 + r], zo0, zo1);
                const int ca = cp * 2, cb = cp * 2 + 1;
                const float h0 = gatef(zi0, zf0, zg0, zo0, creg[ca * 4 + r]);
                const float h1 = gatef(zi1, zf1, zg1, zo1, creg[cb * 4 + r]);
                const int row = r0 + r;
                nA[(DIN + hk0 + ca) * SAS + row] = h0;
                nA[(DIN + hk0 + cb) * SAS + row] = h1;
            }
        }

        // preload x(t+1) into next buffer; single barrier; swap
        if (t + 1 < TT) {
            for (int i = tid; i < DIN * RPB; i += NTH) {
                const int r = i & 31, k = i >> 5;
                const int row = row0 + r;
                float v;
                if (k < OBS) v = traj[((size_t)row * TT + t + 1) * OBS + k];
                else         v = act [((size_t)row * TT + t + 1) * ACTD + (k - OBS)];
                nA[k * SAS + r] = v;
            }
        }
        __syncthreads();
        float* tmp = cA; cA = nA; nA = tmp;
    }

    // ============================ MLP head ============================
    // Thread: 4 rows x 4 cols (c0 = cgrp*4). Per kk: 1 LDS.128 + 1 LDG.128.
    for (int l = 0; l < NL; ++l) {
        const float* Wl = mlpW + (size_t)l * HH * HH + hk0;
        const int c0 = hk0;

        ull acc[8];                        // [cp(2)][r(4)], biases folded in
        {
            const ull b01 = pk2(mlpB[l * HH + c0],     mlpB[l * HH + c0 + 1]);
            const ull b23 = pk2(mlpB[l * HH + c0 + 2], mlpB[l * HH + c0 + 3]);
            #pragma unroll
            for (int r = 0; r < 4; ++r) { acc[r] = b01; acc[4 + r] = b23; }
        }

        #pragma unroll 4
        for (int k = 0; k < HH; ++k) {
            const float4 a = *(const float4*)(cA + (DIN + k) * SAS + r0);
            const ull a0 = pk2(a.x, a.x), a1 = pk2(a.y, a.y);
            const ull a2 = pk2(a.z, a.z), a3 = pk2(a.w, a.w);
            const ulonglong2 w = *(const ulonglong2*)(Wl + (size_t)k * HH);
            ffma2(acc[0], w.x, a0);  ffma2(acc[1], w.x, a1);
            ffma2(acc[2], w.x, a2);  ffma2(acc[3], w.x, a3);
            ffma2(acc[4], w.y, a0);  ffma2(acc[5], w.y, a1);
            ffma2(acc[6], w.y, a2);  ffma2(acc[7], w.y, a3);
        }

        // silu epilogue -> next buffer
        #pragma unroll
        for (int r = 0; r < 4; ++r) {
            float v0, v1, v2, v3;
            upk2(acc[0 + r], v0, v1);
            upk2(acc[4 + r], v2, v3);
            const int row = r0 + r;
            nA[(DIN + c0 + 0) * SAS + row] = v0 * sigf(v0);
            nA[(DIN + c0 + 1) * SAS + row] = v1 * sigf(v1);
            nA[(DIN + c0 + 2) * SAS + row] = v2 * sigf(v2);
            nA[(DIN + c0 + 3) * SAS + row] = v3 * sigf(v3);
        }
        __syncthreads();
        float* tmp = cA; cA = nA; nA = tmp;
    }

    // ---- output layer: [32x256] @ [256x64] + bout; K split across cgrp>>5
    {
        const int khalf = cgrp >> 5;        // 0 or 1
        const int c0    = (cgrp & 31) << 1;
        const float* Wo = Wout + c0;
        const int kb    = khalf << 7;

        ull acco[4];
        const ull binit = khalf ? 0ull : pk2(bout[c0], bout[c0 + 1]);
        #pragma unroll
        for (int i = 0; i < 4; ++i) acco[i] = binit;

        #pragma unroll 4
        for (int k = 0; k < 128; ++k) {
            const float4 a = *(const float4*)(cA + (DIN + kb + k) * SAS + r0);
            const ull w = *(const ull*)(Wo + (size_t)(kb + k) * OUTD);
            ffma2(acco[0], w, pk2(a.x, a.x));
            ffma2(acco[1], w, pk2(a.y, a.y));
            ffma2(acco[2], w, pk2(a.z, a.z));
            ffma2(acco[3], w, pk2(a.w, a.w));
        }
        float* scr = nA;                    // scratch
        if (khalf == 1) {
            #pragma unroll
            for (int r = 0; r < 4; ++r) {
                float v0, v1; upk2(acco[r], v0, v1);
                scr[(c0 + 0) * SAS + r0 + r] = v0;
                scr[(c0 + 1) * SAS + r0 + r] = v1;
            }
        }
        __syncthreads();
        if (khalf == 0) {
            #pragma unroll
            for (int r = 0; r < 4; ++r) {
                float v0, v1; upk2(acco[r], v0, v1);
                v0 += scr[(c0 + 0) * SAS + r0 + r];
                v1 += scr[(c0 + 1) * SAS + r0 + r];
                *(float2*)(out + (size_t)(row0 + r0 + r) * OUTD + c0) =
                    make_float2(v0, v1);
            }
        }
    }
}

extern "C" void kernel_launch(void* const* d_in, const int* in_sizes, int n_in,
                              void* d_out, int out_size)
{
    const float* traj = (const float*)d_in[0];
    const float* act  = (const float*)d_in[1];
    const float* Wi   = (const float*)d_in[2];
    const float* Wh   = (const float*)d_in[3];
    const float* bh   = (const float*)d_in[4];
    const float* mlpW = (const float*)d_in[5];
    const float* mlpB = (const float*)d_in[6];
    const float* Wout = (const float*)d_in[7];
    const float* bout = (const float*)d_in[8];
    float* out = (float*)d_out;

    cudaFuncSetAttribute(lstm_fwd_kernel,
                         cudaFuncAttributeMaxDynamicSharedMemorySize,
                         SMEM_FLOATS * (int)sizeof(float));
    lstm_fwd_kernel<<<NCTA, NTH, SMEM_FLOATS * sizeof(float)>>>(
        traj, act, Wi, Wh, bh, mlpW, mlpB, Wout, bout, out);
}

// round 9
// speedup vs baseline: 1.3334x; 1.3334x over previous
#include <cuda_runtime.h>
#include <cstdint>

// Problem constants
#define BB   4096
#define TT   50
#define OBS  64
#define ACTD 16
#define DIN  80      // OBS + ACT
#define HH   256
#define G4   1024    // 4*H
#define NL   5
#define OUTD 64
#define KTOT 336

// Kernel config
#define RPB  32            // batch rows per CTA
#define NCTA (BB / RPB)    // 128
#define NTH  512
#define NW   16            // warps
#define SAS  36            // sA row stride in floats
#define PAN  24            // panel depth (336 = 14*24)
#define NPAN 14
#define PFLT (PAN * 32)    // floats per panel (per warp)

// Shared memory (floats)
#define OFF_A0 0
#define OFF_A1 (KTOT * SAS)             // 12096
#define OFF_SB (2 * KTOT * SAS)         // 24192
#define OFF_P  (OFF_SB + G4)            // 25216
#define SMEM_FLOATS (OFF_P + NW * 2 * PFLT)   // 49792 floats = 199168 B

typedef unsigned long long ull;

// Repacked LSTM weights: W2[k][cp][g][c]  (k<336, cp<128, g<4, c<2)
__device__ float W2buf[KTOT * G4];

__device__ __forceinline__ float sigf(float x) {
    return __fdividef(1.0f, 1.0f + __expf(-x));
}
__device__ __forceinline__ void ffma2(ull &d, ull a, ull b) {
    asm("fma.rn.f32x2 %0, %1, %2, %0;" : "+l"(d) : "l"(a), "l"(b));
}
__device__ __forceinline__ ull pk2(float lo, float hi) {
    ull r; asm("mov.b64 %0, {%1, %2};" : "=l"(r) : "f"(lo), "f"(hi)); return r;
}
__device__ __forceinline__ void upk2(ull v, float &lo, float &hi) {
    asm("mov.b64 {%0, %1}, %2;" : "=f"(lo), "=f"(hi) : "l"(v));
}
__device__ __forceinline__ uint32_t smem_u32(const void* p) {
    uint32_t a;
    asm("{ .reg .u64 t; cvta.to.shared.u64 t, %1; cvt.u32.u64 %0, t; }"
        : "=r"(a) : "l"(p));
    return a;
}
__device__ __forceinline__ void cpa16(uint32_t s, const float* g) {
    asm volatile("cp.async.cg.shared.global [%0], [%1], 16;" :: "r"(s), "l"(g));
}
#define CP_COMMIT() asm volatile("cp.async.commit_group;" ::: "memory")
#define CP_WAIT(n)  asm volatile("cp.async.wait_group %0;" :: "n"(n) : "memory")

__device__ __forceinline__ float gatef(float zi, float zf, float zg, float zo,
                                       float &c)
{
    const float ig = sigf(zi);
    const float fg = sigf(zf);
    const float gg = zg * sigf(zg);       // silu
    const float og = sigf(zo);
    const float cn = fg * c + ig * gg;
    c = cn;
    return og * cn * sigf(cn);            // o * silu(c_new)
}

// ---------------- prepass: repack [Wi;Wh] gate-interleaved ----------------
__global__ void repack_kernel(const float* __restrict__ Wi,
                              const float* __restrict__ Wh)
{
    const int i = blockIdx.x * blockDim.x + threadIdx.x;
    if (i >= KTOT * G4) return;
    const int k   = i >> 10;
    const int rem = i & 1023;
    const int cp  = rem >> 3;
    const int g   = (rem >> 1) & 3;
    const int c   = rem & 1;
    const int col = (g << 8) + (cp << 1) + c;
    W2buf[i] = (k < DIN) ? Wi[(size_t)k * G4 + col]
                         : Wh[(size_t)(k - DIN) * G4 + col];
}

// prefetch one 24-k x 128B warp panel via cp.async (all 32 lanes, 6 ops each)
__device__ __forceinline__ void prefetch_panel(uint32_t dstb, const float* src,
                                               int lane)
{
    #pragma unroll
    for (int j = 0; j < 6; ++j) {
        const int o  = lane + (j << 5);      // 0..191
        const int kk = o >> 3;
        const int ch = o & 7;
        cpa16(dstb + (uint32_t)(kk * 32 + ch * 4) * 4,
              src + (size_t)kk * G4 + ch * 4);
    }
    CP_COMMIT();
}

__global__ void __launch_bounds__(NTH, 1)
lstm_fwd_kernel(const float* __restrict__ traj, const float* __restrict__ act,
                const float* __restrict__ bh,   const float* __restrict__ mlpW,
                const float* __restrict__ mlpB, const float* __restrict__ Wout,
                const float* __restrict__ bout, float* __restrict__ out)
{
    extern __shared__ float sm[];
    float* sB = sm + OFF_SB;

    const int tid  = threadIdx.x;
    const int lane = tid & 31;
    const int wid  = tid >> 5;       // 0..15
    const int row0 = blockIdx.x * RPB;
    const int rgrp = tid & 7;        // 8 row groups x 4 rows
    const int cgrp = tid >> 3;       // 0..63 (colpair within half)
    const int cgl  = cgrp & 3;       // colpair within warp
    const int r0   = rgrp << 2;

    float* cA = sm + OFF_A0;
    float* nA = sm + OFF_A1;
    float* pwarp = sm + OFF_P + wid * (2 * PFLT);        // warp-private panels
    const uint32_t pwb = smem_u32(pwarp);

    // cell state: creg[half*8 + c*4 + r]
    float creg[16];
    #pragma unroll
    for (int i = 0; i < 16; ++i) creg[i] = 0.0f;

    // init
    for (int i = tid; i < HH * SAS; i += NTH) cA[DIN * SAS + i] = 0.0f;
    for (int i = tid; i < G4; i += NTH) sB[i] = bh[i];
    for (int i = tid; i < DIN * RPB; i += NTH) {
        const int r = i & 31, k = i >> 5;
        const int row = row0 + r;
        float v;
        if (k < OBS) v = traj[((size_t)row * TT) * OBS + k];
        else         v = act [((size_t)row * TT) * ACTD + (k - OBS)];
        cA[k * SAS + r] = v;
    }
    __syncthreads();

    // ============================ LSTM over time ============================
    for (int t = 0; t < TT; ++t) {
        #pragma unroll
        for (int half = 0; half < 2; ++half) {
            const int cpw = (half << 6) + (wid << 2);    // warp's first colpair
            const int hk0 = ((half << 6) + cgrp) << 1;
            const float* wsrc = W2buf + cpw * 8;

            // acc[g*4 + r], bias-initialized
            ull acc[16];
            #pragma unroll
            for (int g = 0; g < 4; ++g) {
                const ull b = pk2(sB[(g << 8) + hk0], sB[(g << 8) + hk0 + 1]);
                acc[g * 4 + 0] = b; acc[g * 4 + 1] = b;
                acc[g * 4 + 2] = b; acc[g * 4 + 3] = b;
            }

            prefetch_panel(pwb, wsrc, lane);
            for (int p = 0; p < NPAN; ++p) {
                if (p + 1 < NPAN) {
                    prefetch_panel(pwb + (((p + 1) & 1) ? PFLT * 4 : 0),
                                   wsrc + (size_t)(p + 1) * PAN * G4, lane);
                    CP_WAIT(1);
                } else {
                    CP_WAIT(0);
                }
                __syncwarp();

                const float* panel = pwarp + ((p & 1) ? PFLT : 0) + cgl * 8;
                const float* aptr  = cA + (p * PAN) * SAS + r0;
                #pragma unroll 4
                for (int kk = 0; kk < PAN; ++kk) {
                    const float4 a = *(const float4*)(aptr);
                    const ull a0 = pk2(a.x, a.x), a1 = pk2(a.y, a.y);
                    const ull a2 = pk2(a.z, a.z), a3 = pk2(a.w, a.w);
                    const ulonglong2 wa = *(const ulonglong2*)(panel + kk * 32);
                    const ulonglong2 wb = *(const ulonglong2*)(panel + kk * 32 + 4);
                    ffma2(acc[ 0], wa.x, a0); ffma2(acc[ 1], wa.x, a1);
                    ffma2(acc[ 2], wa.x, a2); ffma2(acc[ 3], wa.x, a3);
                    ffma2(acc[ 4], wa.y, a0); ffma2(acc[ 5], wa.y, a1);
                    ffma2(acc[ 6], wa.y, a2); ffma2(acc[ 7], wa.y, a3);
                    ffma2(acc[ 8], wb.x, a0); ffma2(acc[ 9], wb.x, a1);
                    ffma2(acc[10], wb.x, a2); ffma2(acc[11], wb.x, a3);
                    ffma2(acc[12], wb.y, a0); ffma2(acc[13], wb.y, a1);
                    ffma2(acc[14], wb.y, a2); ffma2(acc[15], wb.y, a3);
                    aptr += SAS;
                }
                __syncwarp();   // all lanes done with panel before overwrite
            }

            // gate epilogue -> h_new straight into NEXT buffer
            #pragma unroll
            for (int r = 0; r < 4; ++r) {
                float zi0, zi1, zf0, zf1, zg0, zg1, zo0, zo1;
                upk2(acc[ 0 + r], zi0, zi1);
                upk2(acc[ 4 + r], zf0, zf1);
                upk2(acc[ 8 + r], zg0, zg1);
                upk2(acc[12 + r], zo0, zo1);
                const float h0 = gatef(zi0, zf0, zg0, zo0, creg[half * 8 + 0 + r]);
                const float h1 = gatef(zi1, zf1, zg1, zo1, creg[half * 8 + 4 + r]);
                const int row = r0 + r;
                nA[(DIN + hk0)     * SAS + row] = h0;
                nA[(DIN + hk0 + 1) * SAS + row] = h1;
            }
        }

        // preload x(t+1); single barrier; swap
        if (t + 1 < TT) {
            for (int i = tid; i < DIN * RPB; i += NTH) {
                const int r = i & 31, k = i >> 5;
                const int row = row0 + r;
                float v;
                if (k < OBS) v = traj[((size_t)row * TT + t + 1) * OBS + k];
                else         v = act [((size_t)row * TT + t + 1) * ACTD + (k - OBS)];
                nA[k * SAS + r] = v;
            }
        }
        __syncthreads();
        float* tmp = cA; cA = nA; nA = tmp;
    }

    // ============================ MLP head ============================
    // Thread: 4 rows x 4 cols (c0 = cgrp*4). Per kk: 1 LDS.128 + 1 LDG.128.
    for (int l = 0; l < NL; ++l) {
        const float* Wl = mlpW + (size_t)l * HH * HH + (cgrp << 2);
        const int c0 = cgrp << 2;

        ull acc[8];
        {
            const ull b01 = pk2(mlpB[l * HH + c0],     mlpB[l * HH + c0 + 1]);
            const ull b23 = pk2(mlpB[l * HH + c0 + 2], mlpB[l * HH + c0 + 3]);
            #pragma unroll
            for (int r = 0; r < 4; ++r) { acc[r] = b01; acc[4 + r] = b23; }
        }

        #pragma unroll 4
        for (int k = 0; k < HH; ++k) {
            const float4 a = *(const float4*)(cA + (DIN + k) * SAS + r0);
            const ull a0 = pk2(a.x, a.x), a1 = pk2(a.y, a.y);
            const ull a2 = pk2(a.z, a.z), a3 = pk2(a.w, a.w);
            const ulonglong2 w = *(const ulonglong2*)(Wl + (size_t)k * HH);
            ffma2(acc[0], w.x, a0);  ffma2(acc[1], w.x, a1);
            ffma2(acc[2], w.x, a2);  ffma2(acc[3], w.x, a3);
            ffma2(acc[4], w.y, a0);  ffma2(acc[5], w.y, a1);
            ffma2(acc[6], w.y, a2);  ffma2(acc[7], w.y, a3);
        }

        #pragma unroll
        for (int r = 0; r < 4; ++r) {
            float v0, v1, v2, v3;
            upk2(acc[0 + r], v0, v1);
            upk2(acc[4 + r], v2, v3);
            const int row = r0 + r;
            nA[(DIN + c0 + 0) * SAS + row] = v0 * sigf(v0);
            nA[(DIN + c0 + 1) * SAS + row] = v1 * sigf(v1);
            nA[(DIN + c0 + 2) * SAS + row] = v2 * sigf(v2);
            nA[(DIN + c0 + 3) * SAS + row] = v3 * sigf(v3);
        }
        __syncthreads();
        float* tmp = cA; cA = nA; nA = tmp;
    }

    // ---- output layer: [32x256] @ [256x64] + bout; K split across cgrp>>5
    {
        const int khalf = cgrp >> 5;
        const int c0    = (cgrp & 31) << 1;
        const float* Wo = Wout + c0;
        const int kb    = khalf << 7;

        ull acco[4];
        const ull binit = khalf ? 0ull : pk2(bout[c0], bout[c0 + 1]);
        #pragma unroll
        for (int i = 0; i < 4; ++i) acco[i] = binit;

        #pragma unroll 4
        for (int k = 0; k < 128; ++k) {
            const float4 a = *(const float4*)(cA + (DIN + kb + k) * SAS + r0);
            const ull w = *(const ull*)(Wo + (size_t)(kb + k) * OUTD);
            ffma2(acco[0], w, pk2(a.x, a.x));
            ffma2(acco[1], w, pk2(a.y, a.y));
            ffma2(acco[2], w, pk2(a.z, a.z));
            ffma2(acco[3], w, pk2(a.w, a.w));
        }
        float* scr = nA;
        if (khalf == 1) {
            #pragma unroll
            for (int r = 0; r < 4; ++r) {
                float v0, v1; upk2(acco[r], v0, v1);
                scr[(c0 + 0) * SAS + r0 + r] = v0;
                scr[(c0 + 1) * SAS + r0 + r] = v1;
            }
        }
        __syncthreads();
        if (khalf == 0) {
            #pragma unroll
            for (int r = 0; r < 4; ++r) {
                float v0, v1; upk2(acco[r], v0, v1);
                v0 += scr[(c0 + 0) * SAS + r0 + r];
                v1 += scr[(c0 + 1) * SAS + r0 + r];
                *(float2*)(out + (size_t)(row0 + r0 + r) * OUTD + c0) =
                    make_float2(v0, v1);
            }
        }
    }
}

extern "C" void kernel_launch(void* const* d_in, const int* in_sizes, int n_in,
                              void* d_out, int out_size)
{
    const float* traj = (const float*)d_in[0];
    const float* act  = (const float*)d_in[1];
    const float* Wi   = (const float*)d_in[2];
    const float* Wh   = (const float*)d_in[3];
    const float* bh   = (const float*)d_in[4];
    const float* mlpW = (const float*)d_in[5];
    const float* mlpB = (const float*)d_in[6];
    const float* Wout = (const float*)d_in[7];
    const float* bout = (const float*)d_in[8];
    float* out = (float*)d_out;

    repack_kernel<<<(KTOT * G4 + 511) / 512, 512>>>(Wi, Wh);

    cudaFuncSetAttribute(lstm_fwd_kernel,
                         cudaFuncAttributeMaxDynamicSharedMemorySize,
                         SMEM_FLOATS * (int)sizeof(float));
    lstm_fwd_kernel<<<NCTA, NTH, SMEM_FLOATS * sizeof(float)>>>(
        traj, act, bh, mlpW, mlpB, Wout, bout, out);
}

// round 10
// speedup vs baseline: 1.3895x; 1.0420x over previous
#include <cuda_runtime.h>
#include <cstdint>

// Problem constants
#define BB   4096
#define TT   50
#define OBS  64
#define ACTD 16
#define DIN  80      // OBS + ACT
#define HH   256
#define G4   1024    // 4*H
#define NL   5
#define OUTD 64
#define KTOT 336

// Kernel config
#define RPB  32            // batch rows per CTA
#define NCTA (BB / RPB)    // 128
#define NTH  512
#define NW   16            // warps
#define SAS  36            // sA row stride in floats
#define PAN  12            // panel depth (336 = 28*12)
#define NPAN 28
#define PFLT (PAN * 64)    // floats per warp panel (both halves)

// Shared memory (floats)
#define OFF_A0 0
#define OFF_A1 (KTOT * SAS)             // 12096
#define OFF_SB (2 * KTOT * SAS)         // 24192
#define OFF_P  (OFF_SB + G4)            // 25216
#define SMEM_FLOATS (OFF_P + NW * 2 * PFLT)   // 49792 floats = 199168 B

typedef unsigned long long ull;

// Repacked LSTM weights: W3[k][wid][half][j][g][c]
//   k<336, wid<16, half<2, j<4 (colpair in warp), g<4, c<2  -> 64 floats/(k,wid)
__device__ float W3buf[KTOT * G4];

__device__ __forceinline__ float sigf(float x) {
    return __fdividef(1.0f, 1.0f + __expf(-x));
}
__device__ __forceinline__ void ffma2(ull &d, ull a, ull b) {
    asm("fma.rn.f32x2 %0, %1, %2, %0;" : "+l"(d) : "l"(a), "l"(b));
}
__device__ __forceinline__ ull pk2(float lo, float hi) {
    ull r; asm("mov.b64 %0, {%1, %2};" : "=l"(r) : "f"(lo), "f"(hi)); return r;
}
__device__ __forceinline__ void upk2(ull v, float &lo, float &hi) {
    asm("mov.b64 {%0, %1}, %2;" : "=f"(lo), "=f"(hi) : "l"(v));
}
__device__ __forceinline__ uint32_t smem_u32(const void* p) {
    uint32_t a;
    asm("{ .reg .u64 t; cvta.to.shared.u64 t, %1; cvt.u32.u64 %0, t; }"
        : "=r"(a) : "l"(p));
    return a;
}
__device__ __forceinline__ void cpa16(uint32_t s, const float* g) {
    asm volatile("cp.async.cg.shared.global [%0], [%1], 16;" :: "r"(s), "l"(g));
}
#define CP_COMMIT() asm volatile("cp.async.commit_group;" ::: "memory")
#define CP_WAIT(n)  asm volatile("cp.async.wait_group %0;" :: "n"(n) : "memory")

__device__ __forceinline__ float gatef(float zi, float zf, float zg, float zo,
                                       float &c)
{
    const float ig = sigf(zi);
    const float fg = sigf(zf);
    const float gg = zg * sigf(zg);       // silu
    const float og = sigf(zo);
    const float cn = fg * c + ig * gg;
    c = cn;
    return og * cn * sigf(cn);            // o * silu(c_new)
}

// ---------------- prepass: repack [Wi;Wh] warp-blocked, both halves --------
__global__ void repack_kernel(const float* __restrict__ Wi,
                              const float* __restrict__ Wh)
{
    const int i = blockIdx.x * blockDim.x + threadIdx.x;
    if (i >= KTOT * G4) return;
    const int k    = i >> 10;
    const int rem  = i & 1023;
    const int wid  = rem >> 6;
    const int r6   = rem & 63;
    const int half = r6 >> 5;
    const int j    = (r6 >> 3) & 3;
    const int g    = (r6 >> 1) & 3;
    const int c    = r6 & 1;
    const int col  = (g << 8) + (half << 7) + (wid << 3) + (j << 1) + c;
    W3buf[i] = (k < DIN) ? Wi[(size_t)k * G4 + col]
                         : Wh[(size_t)(k - DIN) * G4 + col];
}

// prefetch one 12-k x 256B warp panel (3072B) via cp.async: 6 ops per lane
__device__ __forceinline__ void prefetch_panel(uint32_t dstb, const float* src,
                                               int lane)
{
    #pragma unroll
    for (int j = 0; j < 6; ++j) {
        const int o  = lane + (j << 5);      // 0..191
        const int kk = o >> 4;               // 12 k rows
        const int ch = o & 15;               // 16 chunks of 16B
        cpa16(dstb + (uint32_t)(kk * 64 + ch * 4) * 4,
              src + (size_t)kk * G4 + ch * 4);
    }
    CP_COMMIT();
}

__global__ void __launch_bounds__(NTH, 1)
lstm_fwd_kernel(const float* __restrict__ traj, const float* __restrict__ act,
                const float* __restrict__ bh,   const float* __restrict__ mlpW,
                const float* __restrict__ mlpB, const float* __restrict__ Wout,
                const float* __restrict__ bout, float* __restrict__ out)
{
    extern __shared__ float sm[];
    float* sB = sm + OFF_SB;

    const int tid  = threadIdx.x;
    const int lane = tid & 31;
    const int wid  = tid >> 5;       // 0..15
    const int row0 = blockIdx.x * RPB;
    const int rgrp = tid & 7;        // 8 row groups x 4 rows
    const int cgrp = tid >> 3;       // 0..63
    const int cgl  = cgrp & 3;       // colpair within warp
    const int r0   = rgrp << 2;

    float* cA = sm + OFF_A0;
    float* nA = sm + OFF_A1;
    float* pwarp = sm + OFF_P + wid * (2 * PFLT);
    const uint32_t pwb = smem_u32(pwarp);
    const float* wsrc = W3buf + (wid << 6);     // + k*1024

    // thread's hk cols: half h -> h*128 + (wid*4+cgl)*2 + {0,1}
    const int hkb = ((wid << 2) + cgl) << 1;

    // cell state: creg[half*8 + c*4 + r]
    float creg[16];
    #pragma unroll
    for (int i = 0; i < 16; ++i) creg[i] = 0.0f;

    // init
    for (int i = tid; i < HH * SAS; i += NTH) cA[DIN * SAS + i] = 0.0f;
    for (int i = tid; i < G4; i += NTH) sB[i] = bh[i];
    for (int i = tid; i < DIN * RPB; i += NTH) {
        const int r = i & 31, k = i >> 5;
        const int row = row0 + r;
        float v;
        if (k < OBS) v = traj[((size_t)row * TT) * OBS + k];
        else         v = act [((size_t)row * TT) * ACTD + (k - OBS)];
        cA[k * SAS + r] = v;
    }
    __syncthreads();

    // ============================ LSTM over time ============================
    for (int t = 0; t < TT; ++t) {
        // acc[half*16 + g*4 + r], bias-initialized
        ull acc[32];
        #pragma unroll
        for (int half = 0; half < 2; ++half) {
            const int hk0 = (half << 7) + hkb;
            #pragma unroll
            for (int g = 0; g < 4; ++g) {
                const ull b = pk2(sB[(g << 8) + hk0], sB[(g << 8) + hk0 + 1]);
                acc[half * 16 + g * 4 + 0] = b;
                acc[half * 16 + g * 4 + 1] = b;
                acc[half * 16 + g * 4 + 2] = b;
                acc[half * 16 + g * 4 + 3] = b;
            }
        }

        prefetch_panel(pwb, wsrc, lane);
        for (int p = 0; p < NPAN; ++p) {
            if (p + 1 < NPAN) {
                prefetch_panel(pwb + (((p + 1) & 1) ? PFLT * 4 : 0),
                               wsrc + (size_t)(p + 1) * PAN * G4, lane);
                CP_WAIT(1);
            } else {
                CP_WAIT(0);
            }
            __syncwarp();

            const float* panel = pwarp + ((p & 1) ? PFLT : 0) + (cgl << 3);
            const float* aptr  = cA + (p * PAN) * SAS + r0;
            #pragma unroll 4
            for (int kk = 0; kk < PAN; ++kk) {
                const float4 a = *(const float4*)(aptr);
                const ull a0 = pk2(a.x, a.x), a1 = pk2(a.y, a.y);
                const ull a2 = pk2(a.z, a.z), a3 = pk2(a.w, a.w);
                const float* pr = panel + kk * 64;
                const ulonglong2 w01 = *(const ulonglong2*)(pr);        // h0 g0,g1
                const ulonglong2 w23 = *(const ulonglong2*)(pr + 4);    // h0 g2,g3
                const ulonglong2 w45 = *(const ulonglong2*)(pr + 32);   // h1 g0,g1
                const ulonglong2 w67 = *(const ulonglong2*)(pr + 36);   // h1 g2,g3
                ffma2(acc[ 0], w01.x, a0); ffma2(acc[ 1], w01.x, a1);
                ffma2(acc[ 2], w01.x, a2); ffma2(acc[ 3], w01.x, a3);
                ffma2(acc[ 4], w01.y, a0); ffma2(acc[ 5], w01.y, a1);
                ffma2(acc[ 6], w01.y, a2); ffma2(acc[ 7], w01.y, a3);
                ffma2(acc[ 8], w23.x, a0); ffma2(acc[ 9], w23.x, a1);
                ffma2(acc[10], w23.x, a2); ffma2(acc[11], w23.x, a3);
                ffma2(acc[12], w23.y, a0); ffma2(acc[13], w23.y, a1);
                ffma2(acc[14], w23.y, a2); ffma2(acc[15], w23.y, a3);
                ffma2(acc[16], w45.x, a0); ffma2(acc[17], w45.x, a1);
                ffma2(acc[18], w45.x, a2); ffma2(acc[19], w45.x, a3);
                ffma2(acc[20], w45.y, a0); ffma2(acc[21], w45.y, a1);
                ffma2(acc[22], w45.y, a2); ffma2(acc[23], w45.y, a3);
                ffma2(acc[24], w67.x, a0); ffma2(acc[25], w67.x, a1);
                ffma2(acc[26], w67.x, a2); ffma2(acc[27], w67.x, a3);
                ffma2(acc[28], w67.y, a0); ffma2(acc[29], w67.y, a1);
                ffma2(acc[30], w67.y, a2); ffma2(acc[31], w67.y, a3);
                aptr += SAS;
            }
            __syncwarp();
        }

        // gate epilogue (both halves) -> h_new into NEXT buffer
        #pragma unroll
        for (int half = 0; half < 2; ++half) {
            const int hk0 = (half << 7) + hkb;
            #pragma unroll
            for (int r = 0; r < 4; ++r) {
                float zi0, zi1, zf0, zf1, zg0, zg1, zo0, zo1;
                upk2(acc[half * 16 +  0 + r], zi0, zi1);
                upk2(acc[half * 16 +  4 + r], zf0, zf1);
                upk2(acc[half * 16 +  8 + r], zg0, zg1);
                upk2(acc[half * 16 + 12 + r], zo0, zo1);
                const float h0 = gatef(zi0, zf0, zg0, zo0, creg[half * 8 + 0 + r]);
                const float h1 = gatef(zi1, zf1, zg1, zo1, creg[half * 8 + 4 + r]);
                const int row = r0 + r;
                nA[(DIN + hk0)     * SAS + row] = h0;
                nA[(DIN + hk0 + 1) * SAS + row] = h1;
            }
        }

        // preload x(t+1); single barrier; swap
        if (t + 1 < TT) {
            for (int i = tid; i < DIN * RPB; i += NTH) {
                const int r = i & 31, k = i >> 5;
                const int row = row0 + r;
                float v;
                if (k < OBS) v = traj[((size_t)row * TT + t + 1) * OBS + k];
                else         v = act [((size_t)row * TT + t + 1) * ACTD + (k - OBS)];
                nA[k * SAS + r] = v;
            }
        }
        __syncthreads();
        float* tmp = cA; cA = nA; nA = tmp;
    }

    // ============================ MLP head ============================
    for (int l = 0; l < NL; ++l) {
        const float* Wl = mlpW + (size_t)l * HH * HH + (cgrp << 2);
        const int c0 = cgrp << 2;

        ull acc[8];
        {
            const ull b01 = pk2(mlpB[l * HH + c0],     mlpB[l * HH + c0 + 1]);
            const ull b23 = pk2(mlpB[l * HH + c0 + 2], mlpB[l * HH + c0 + 3]);
            #pragma unroll
            for (int r = 0; r < 4; ++r) { acc[r] = b01; acc[4 + r] = b23; }
        }

        #pragma unroll 4
        for (int k = 0; k < HH; ++k) {
            const float4 a = *(const float4*)(cA + (DIN + k) * SAS + r0);
            const ull a0 = pk2(a.x, a.x), a1 = pk2(a.y, a.y);
            const ull a2 = pk2(a.z, a.z), a3 = pk2(a.w, a.w);
            const ulonglong2 w = *(const ulonglong2*)(Wl + (size_t)k * HH);
            ffma2(acc[0], w.x, a0);  ffma2(acc[1], w.x, a1);
            ffma2(acc[2], w.x, a2);  ffma2(acc[3], w.x, a3);
            ffma2(acc[4], w.y, a0);  ffma2(acc[5], w.y, a1);
            ffma2(acc[6], w.y, a2);  ffma2(acc[7], w.y, a3);
        }

        #pragma unroll
        for (int r = 0; r < 4; ++r) {
            float v0, v1, v2, v3;
            upk2(acc[0 + r], v0, v1);
            upk2(acc[4 + r], v2, v3);
            const int row = r0 + r;
            nA[(DIN + c0 + 0) * SAS + row] = v0 * sigf(v0);
            nA[(DIN + c0 + 1) * SAS + row] = v1 * sigf(v1);
            nA[(DIN + c0 + 2) * SAS + row] = v2 * sigf(v2);
            nA[(DIN + c0 + 3) * SAS + row] = v3 * sigf(v3);
        }
        __syncthreads();
        float* tmp = cA; cA = nA; nA = tmp;
    }

    // ---- output layer: [32x256] @ [256x64] + bout; K split across cgrp>>5
    {
        const int khalf = cgrp >> 5;
        const int c0    = (cgrp & 31) << 1;
        const float* Wo = Wout + c0;
        const int kb    = khalf << 7;

        ull acco[4];
        const ull binit = khalf ? 0ull : pk2(bout[c0], bout[c0 + 1]);
        #pragma unroll
        for (int i = 0; i < 4; ++i) acco[i] = binit;

        #pragma unroll 4
        for (int k = 0; k < 128; ++k) {
            const float4 a = *(const float4*)(cA + (DIN + kb + k) * SAS + r0);
            const ull w = *(const ull*)(Wo + (size_t)(kb + k) * OUTD);
            ffma2(acco[0], w, pk2(a.x, a.x));
            ffma2(acco[1], w, pk2(a.y, a.y));
            ffma2(acco[2], w, pk2(a.z, a.z));
            ffma2(acco[3], w, pk2(a.w, a.w));
        }
        float* scr = nA;
        if (khalf == 1) {
            #pragma unroll
            for (int r = 0; r < 4; ++r) {
                float v0, v1; upk2(acco[r], v0, v1);
                scr[(c0 + 0) * SAS + r0 + r] = v0;
                scr[(c0 + 1) * SAS + r0 + r] = v1;
            }
        }
        __syncthreads();
        if (khalf == 0) {
            #pragma unroll
            for (int r = 0; r < 4; ++r) {
                float v0, v1; upk2(acco[r], v0, v1);
                v0 += scr[(c0 + 0) * SAS + r0 + r];
                v1 += scr[(c0 + 1) * SAS + r0 + r];
                *(float2*)(out + (size_t)(row0 + r0 + r) * OUTD + c0) =
                    make_float2(v0, v1);
            }
        }
    }
}

extern "C" void kernel_launch(void* const* d_in, const int* in_sizes, int n_in,
                              void* d_out, int out_size)
{
    const float* traj = (const float*)d_in[0];
    const float* act  = (const float*)d_in[1];
    const float* Wi   = (const float*)d_in[2];
    const float* Wh   = (const float*)d_in[3];
    const float* bh   = (const float*)d_in[4];
    const float* mlpW = (const float*)d_in[5];
    const float* mlpB = (const float*)d_in[6];
    const float* Wout = (const float*)d_in[7];
    const float* bout = (const float*)d_in[8];
    float* out = (float*)d_out;

    repack_kernel<<<(KTOT * G4 + 511) / 512, 512>>>(Wi, Wh);

    cudaFuncSetAttribute(lstm_fwd_kernel,
                         cudaFuncAttributeMaxDynamicSharedMemorySize,
                         SMEM_FLOATS * (int)sizeof(float));
    lstm_fwd_kernel<<<NCTA, NTH, SMEM_FLOATS * sizeof(float)>>>(
        traj, act, bh, mlpW, mlpB, Wout, bout, out);
}